// round 16
// baseline (speedup 1.0000x reference)
#include <cuda_runtime.h>
#include <cuda_bf16.h>
#include <cuda_fp16.h>
#include <cstdint>
#include <math_constants.h>

#define CD    256
#define NPIX  65536
#define NCODE 1024
#define PATCH 48
#define CAND_CAP (1<<22)
#define TAU 1.5e-3f
#define KZ_SMEM (2*48*132*4)

__device__ float g_Wcomb[PATCH*CD];
__device__ float g_bcomb[CD];
__device__ float g_cnorm[NCODE];
__device__ float g_Gt[PATCH*CD];
__device__ float g_h[PATCH];
__device__ float g_cb3[NCODE*PATCH];
__device__ float g_z[NPIX*CD];
__device__ __nv_bfloat16 g_zh[NPIX*CD];
__device__ __nv_bfloat16 g_cbh[NCODE*CD];
__device__ float g_znpart[NPIX*2];
__device__ float g_znorm[NPIX];
__device__ int   g_idx[NPIX];
__device__ float g_idxf_dummy[NPIX];
__device__ float g_part[256];
__device__ unsigned long long g_key[NPIX];
__device__ unsigned int g_cand[CAND_CAP];
__device__ int g_ncand;

__device__ __forceinline__ uint32_t bf2pack(float lo, float hi){
    uint32_t r; asm("cvt.rn.bf16x2.f32 %0, %1, %2;" : "=r"(r) : "f"(hi), "f"(lo)); return r;
}
__device__ __forceinline__ uint32_t h2pack(float lo, float hi){
    __half2 h = __floats2half2_rn(lo, hi);
    return *reinterpret_cast<uint32_t*>(&h);
}
__device__ __forceinline__ unsigned encf(float f){
    unsigned b = __float_as_uint(f);
    return (b & 0x80000000u) ? ~b : (b | 0x80000000u);
}
__device__ __forceinline__ float decf(unsigned u){
    return __uint_as_float((u & 0x80000000u) ? (u ^ 0x80000000u) : ~u);
}
__device__ __forceinline__ uint32_t cvta_s(const void* p){
    uint32_t a; asm("{ .reg .u64 t; cvta.to.shared.u64 t, %1; cvt.u32.u64 %0, t; }":"=r"(a):"l"(p)); return a;
}
__device__ __forceinline__ uint64_t pk2(float a){
    uint64_t r; asm("mov.b64 %0,{%1,%1};":"=l"(r):"r"(__float_as_uint(a))); return r;
}
__device__ __forceinline__ uint64_t pk2b(float lo, float hi){
    uint64_t r; asm("mov.b64 %0,{%1,%2};":"=l"(r):"r"(__float_as_uint(lo)),"r"(__float_as_uint(hi))); return r;
}
__device__ __forceinline__ void ffma2(uint64_t& c, uint64_t a, uint64_t b){
    asm("fma.rn.f32x2 %0,%1,%2,%3;":"=l"(c):"l"(a),"l"(b),"l"(c));
}
__device__ __forceinline__ void upk2(uint64_t v, float& lo, float& hi){
    uint32_t l,h; asm("mov.b64 {%0,%1},%2;":"=r"(l),"=r"(h):"l"(v));
    lo=__uint_as_float(l); hi=__uint_as_float(h);
}
#define LDM_X4(R0,R1,R2,R3,ADDR) \
    asm volatile("ldmatrix.sync.aligned.m8n8.x4.shared.b16 {%0,%1,%2,%3}, [%4];" \
        : "=r"(R0), "=r"(R1), "=r"(R2), "=r"(R3) : "r"(ADDR))

// blocks: [0,49) comb, [49,53) cnorm, [53,181) cbh x8, [181,437) key reset
__global__ void k_prep(const float* __restrict__ enc_w, const float* __restrict__ enc_b,
                       const float* __restrict__ w1, const float* __restrict__ b1,
                       const float* __restrict__ cb){
    int bx = blockIdx.x, t = threadIdx.x;
    if (bx < 49) {
        __shared__ float col[CD];
        int p = bx;
        col[t] = (p < PATCH) ? enc_w[t*PATCH+p] : enc_b[t];
        __syncthreads();
        int c = t;
        float s = (p < PATCH) ? 0.f : b1[c];
        for (int o = 0; o < CD; o += 4) {
            float4 wv = *(const float4*)&w1[c*CD+o];
            s = __fmaf_rn(col[o],   wv.x, s);
            s = __fmaf_rn(col[o+1], wv.y, s);
            s = __fmaf_rn(col[o+2], wv.z, s);
            s = __fmaf_rn(col[o+3], wv.w, s);
        }
        if (p < PATCH) g_Wcomb[p*CD+c] = s; else g_bcomb[c] = s;
    } else if (bx < 53) {
        int k = (bx-49)*256 + t;
        const float* r = cb + k*CD; float s = 0.f;
        for (int j = 0; j < CD; j += 4) {
            float4 v = *(const float4*)(r+j);
            s += v.x*v.x + v.y*v.y + v.z*v.z + v.w*v.w;
        }
        g_cnorm[k] = s;
    } else if (bx < 181) {
        int i = ((bx-53)*256 + t)*8;
        float4 a = *(const float4*)&cb[i];
        float4 b = *(const float4*)&cb[i+4];
        *(uint4*)(g_cbh + i) = make_uint4(bf2pack(a.x,a.y), bf2pack(a.z,a.w),
                                          bf2pack(b.x,b.y), bf2pack(b.z,b.w));
    } else {
        int n = (bx-181)*256 + t;
        g_key[n] = ~0ull;
        if (n == 0) g_ncand = 0;
    }
}

// Gt[q][j] = sum_c w2[c][j]*dwf[c][q]; h[q] = sum_c b2[c]*dwf[c][q]
__global__ void k_G(const float* __restrict__ w2, const float* __restrict__ dw,
                    const float* __restrict__ b2){
    int q = blockIdx.x;
    if (q < PATCH) {
        int o=q>>4, rr=q&15, ki=rr>>2, kj=rr&3;
        int qf = o*16 + (3-ki)*4 + (3-kj);
        int j = threadIdx.x;
        float s = 0.f;
        for (int c = 0; c < CD; ++c) s += w2[c*CD+j]*dw[c*PATCH+qf];
        g_Gt[q*CD+j] = s;
    } else if (threadIdx.x < PATCH) {
        int t = threadIdx.x;
        int o=t>>4, rr=t&15, ki=rr>>2, kj=rr&3;
        int qf = o*16 + (3-ki)*4 + (3-kj);
        float s = 0.f;
        for (int c = 0; c < CD; ++c) s += b2[c]*dw[c*PATCH+qf];
        g_h[t] = s;
    }
}

// cb3[k][q] = cb[k] . Gt[q] + h[q]
__global__ void k_cb3(const float* __restrict__ cb){
    __shared__ float row[CD];
    int k = blockIdx.x, t = threadIdx.x;
    for (int c = t; c < CD; c += 192) row[c] = cb[k*CD+c];
    __syncthreads();
    int q = t>>2, part = t&3;
    float s = 0.f;
    for (int c = part; c < CD; c += 4) s += row[c]*g_Gt[q*CD+c];
    s += __shfl_down_sync(0xffffffffu, s, 2, 4);
    s += __shfl_down_sync(0xffffffffu, s, 1, 4);
    if (!part) g_cb3[k*PATCH+q] = s + g_h[q];
}

// z GEMM: 128x128 tile, 8x8 split microtile, f32x2; dynamic smem (50688B)
__global__ void __launch_bounds__(256,1) k_z(const float* __restrict__ x){
    extern __shared__ float zsm[];
    float* Pt = zsm;              // [48][132]
    float* Ws = zsm + 48*132;     // [48][132]
    int tx = threadIdx.x & 15, ty = threadIdx.x >> 4;
    int m0 = blockIdx.x*128, n0 = blockIdx.y*128;
    {
        int b = m0>>12, i0 = (m0&4095)>>6;
        for (int e = threadIdx.x; e < 1536; e += 256) {
            int r = e>>7, pix = e&127;           // r = cin*4+ki
            int cin = r>>2, ki = r&3;
            int i = i0 + (pix>>6), j = pix&63;
            float4 v = *(const float4*)&x[(((b*3+cin)<<8) + (i*4+ki))*256 + j*4];
            Pt[(r*4+0)*132+pix]=v.x; Pt[(r*4+1)*132+pix]=v.y;
            Pt[(r*4+2)*132+pix]=v.z; Pt[(r*4+3)*132+pix]=v.w;
        }
    }
    for (int e = threadIdx.x; e < 1536; e += 256) {
        int row = e>>5, q = e&31;
        *(float4*)&Ws[row*132 + q*4] = *(const float4*)&g_Wcomb[row*CD + n0 + q*4];
    }
    __syncthreads();
    uint64_t acc[8][4];
    #pragma unroll
    for (int i = 0; i < 8; ++i)
        #pragma unroll
        for (int j = 0; j < 4; ++j) acc[i][j] = 0ull;
    #pragma unroll 4
    for (int k = 0; k < 48; ++k) {
        float4 a0 = *(const float4*)&Pt[k*132 + ty*4];
        float4 a1 = *(const float4*)&Pt[k*132 + 64 + ty*4];
        float4 b0 = *(const float4*)&Ws[k*132 + tx*4];
        float4 b1 = *(const float4*)&Ws[k*132 + 64 + tx*4];
        uint64_t bp[4] = { pk2b(b0.x,b0.y), pk2b(b0.z,b0.w),
                           pk2b(b1.x,b1.y), pk2b(b1.z,b1.w) };
        float av[8] = {a0.x,a0.y,a0.z,a0.w, a1.x,a1.y,a1.z,a1.w};
        #pragma unroll
        for (int i = 0; i < 8; ++i) {
            uint64_t ai = pk2(av[i]);
            #pragma unroll
            for (int j = 0; j < 4; ++j) ffma2(acc[i][j], ai, bp[j]);
        }
    }
    float bs[8];
    #pragma unroll
    for (int c = 0; c < 4; ++c) { bs[c] = g_bcomb[n0+tx*4+c]; bs[4+c] = g_bcomb[n0+64+tx*4+c]; }
    #pragma unroll
    for (int i = 0; i < 8; ++i) {
        size_t row = m0 + ((i<4) ? (ty*4+i) : (64+ty*4+i-4));
        float v[8];
        upk2(acc[i][0], v[0], v[1]); upk2(acc[i][1], v[2], v[3]);
        upk2(acc[i][2], v[4], v[5]); upk2(acc[i][3], v[6], v[7]);
        #pragma unroll
        for (int c = 0; c < 8; ++c) v[c] += bs[c];
        float4 o0 = make_float4(v[0],v[1],v[2],v[3]);
        float4 o1 = make_float4(v[4],v[5],v[6],v[7]);
        *(float4*)&g_z[row*CD + n0+tx*4] = o0;
        *(float4*)&g_z[row*CD + n0+64+tx*4] = o1;
        *(uint2*)(g_zh + row*CD + n0+tx*4)    = make_uint2(bf2pack(v[0],v[1]), bf2pack(v[2],v[3]));
        *(uint2*)(g_zh + row*CD + n0+64+tx*4) = make_uint2(bf2pack(v[4],v[5]), bf2pack(v[6],v[7]));
        float s = ((v[0]*v[0]+v[1]*v[1])+(v[2]*v[2]+v[3]*v[3]))
                + ((v[4]*v[4]+v[5]*v[5])+(v[6]*v[6]+v[7]*v[7]));
        s += __shfl_down_sync(0xffffffffu, s, 8, 16);
        s += __shfl_down_sync(0xffffffffu, s, 4, 16);
        s += __shfl_down_sync(0xffffffffu, s, 2, 16);
        s += __shfl_down_sync(0xffffffffu, s, 1, 16);
        if (!tx) g_znpart[row*2 + blockIdx.y] = s;
    }
}

// ---- HMMA approx scores (fp16 score storage); znorm finalize at head ----
#define SS_STRIDE 1032
#define AS_STRIDE 264
#define BS_STRIDE 72
#define AS_OFF 132096
#define BS_OFF (AS_OFF + 64*AS_STRIDE*2)
#define RM_OFF (BS_OFF + 256*BS_STRIDE*2)
#define SC_SMEM (RM_OFF + 256)

__device__ __forceinline__ void fetchB(uint4* pf, int tid, int cp, int kc){
    #pragma unroll
    for (int u = 0; u < 8; ++u) {
        int tt = tid + u*256, row = tt>>3, q = tt&7;
        pf[u] = *((const uint4*)(g_cbh + (size_t)(cp*256+row)*CD + kc*64) + q);
    }
}

__global__ void __launch_bounds__(256,1) k_score(){
    extern __shared__ char smraw[];
    __half* Ss = (__half*)smraw;
    __nv_bfloat16* As = (__nv_bfloat16*)(smraw + AS_OFF);
    __nv_bfloat16* Bs = (__nv_bfloat16*)(smraw + BS_OFF);
    unsigned* RM = (unsigned*)(smraw + RM_OFF);
    int tid = threadIdx.x, w = tid>>5, lane = tid&31;
    int grp = lane>>2, tig = lane&3;
    int lr = lane&7, lm = lane>>3;
    int r0 = blockIdx.x*64;
    if (tid < 64) {
        float2 p = *(const float2*)&g_znpart[(size_t)(r0+tid)*2];
        g_znorm[r0+tid] = __fadd_rn(p.x, p.y);
        RM[tid] = 0u;
    }
    for (int t = tid; t < 2048; t += 256) {
        int row = t>>5, q = t&31;
        *(uint4*)(As + row*AS_STRIDE + q*8) = *((const uint4*)(g_zh + (size_t)(r0+row)*CD) + q);
    }
    uint32_t As_sm = cvta_s(As), Bs_sm = cvta_s(Bs);
    uint32_t aBase = As_sm + (uint32_t)((((lm&1)*8 + lr)*AS_STRIDE + (lm>>1)*8)*2);
    uint32_t bBase = Bs_sm + (uint32_t)(((w*32 + (lm>>1)*8 + lr)*BS_STRIDE + (lm&1)*8)*2);
    unsigned lmax[8];
    #pragma unroll
    for (int i = 0; i < 8; ++i) lmax[i] = 0u;
    uint4 pf[8];
    fetchB(pf, tid, 0, 0);

    for (int cp = 0; cp < 4; ++cp) {
        float acc[4][4][4];
        #pragma unroll
        for (int i = 0; i < 4; ++i)
            #pragma unroll
            for (int j = 0; j < 4; ++j)
                #pragma unroll
                for (int q = 0; q < 4; ++q) acc[i][j][q] = 0.f;
        for (int kc = 0; kc < 4; ++kc) {
            __syncthreads();
            #pragma unroll
            for (int u = 0; u < 8; ++u) {
                int tt = tid + u*256, row = tt>>3, q = tt&7;
                *(uint4*)(Bs + row*BS_STRIDE + q*8) = pf[u];
            }
            int ch = cp*4 + kc + 1;
            if (ch < 16) fetchB(pf, tid, ch>>2, ch&3);
            __syncthreads();
            #pragma unroll
            for (int k16 = 0; k16 < 4; ++k16) {
                uint32_t a[4][4], bp[2][4];
                #pragma unroll
                for (int i = 0; i < 4; ++i)
                    LDM_X4(a[i][0], a[i][1], a[i][2], a[i][3],
                           aBase + (uint32_t)((i*16*AS_STRIDE + kc*64 + k16*16)*2));
                #pragma unroll
                for (int jp = 0; jp < 2; ++jp)
                    LDM_X4(bp[jp][0], bp[jp][1], bp[jp][2], bp[jp][3],
                           bBase + (uint32_t)((jp*16*BS_STRIDE + k16*16)*2));
                #pragma unroll
                for (int i = 0; i < 4; ++i)
                    #pragma unroll
                    for (int j = 0; j < 4; ++j)
                        asm volatile(
                            "mma.sync.aligned.m16n8k16.row.col.f32.bf16.bf16.f32 "
                            "{%0,%1,%2,%3}, {%4,%5,%6,%7}, {%8,%9}, {%0,%1,%2,%3};"
                            : "+f"(acc[i][j][0]), "+f"(acc[i][j][1]),
                              "+f"(acc[i][j][2]), "+f"(acc[i][j][3])
                            : "r"(a[i][0]), "r"(a[i][1]), "r"(a[i][2]), "r"(a[i][3]),
                              "r"(bp[j>>1][(j&1)*2]), "r"(bp[j>>1][(j&1)*2+1]));
            }
        }
        #pragma unroll
        for (int i = 0; i < 4; ++i)
            #pragma unroll
            for (int j = 0; j < 4; ++j) {
                int c_lo = cp*256 + w*32 + j*8 + tig*2;
                float cn0 = 0.5f*g_cnorm[c_lo], cn1 = 0.5f*g_cnorm[c_lo+1];
                float s00 = acc[i][j][0] - cn0, s01 = acc[i][j][1] - cn1;
                float s10 = acc[i][j][2] - cn0, s11 = acc[i][j][3] - cn1;
                int rlo = i*16+grp, rhi = rlo+8;
                *(uint32_t*)(Ss + rlo*SS_STRIDE + c_lo) = h2pack(s00, s01);
                *(uint32_t*)(Ss + rhi*SS_STRIDE + c_lo) = h2pack(s10, s11);
                lmax[i*2]   = max(lmax[i*2],   encf(fmaxf(s00, s01)));
                lmax[i*2+1] = max(lmax[i*2+1], encf(fmaxf(s10, s11)));
            }
    }
    #pragma unroll
    for (int i = 0; i < 4; ++i) {
        atomicMax(&RM[i*16+grp],   lmax[i*2]);
        atomicMax(&RM[i*16+8+grp], lmax[i*2+1]);
    }
    __syncthreads();
    int row = tid>>2, cbase = (tid&3)*256;
    float thr = decf(RM[row]) - TAU;
    const uint4* sp = (const uint4*)(Ss + row*SS_STRIDE + cbase);
    int cnt = 0;
    for (int it = 0; it < 32; ++it) {
        uint4 v = sp[it];
        uint32_t ws[4] = {v.x, v.y, v.z, v.w};
        #pragma unroll
        for (int h = 0; h < 4; ++h) {
            float2 f = __half22float2(*reinterpret_cast<const __half2*>(&ws[h]));
            if (f.x >= thr) ++cnt;
            if (f.y >= thr) ++cnt;
        }
    }
    int incl = cnt;
    #pragma unroll
    for (int o = 1; o < 32; o <<= 1) {
        int t2 = __shfl_up_sync(0xffffffffu, incl, o);
        if (lane >= o) incl += t2;
    }
    int total = __shfl_sync(0xffffffffu, incl, 31);
    int base = 0;
    if (lane == 31 && total) base = atomicAdd(&g_ncand, total);
    base = __shfl_sync(0xffffffffu, base, 31);
    int pos = base + incl - cnt;
    if (total) {
        for (int it = 0; it < 32; ++it) {
            uint4 v = sp[it];
            uint32_t ws[4] = {v.x, v.y, v.z, v.w};
            #pragma unroll
            for (int h = 0; h < 4; ++h) {
                int c = cbase + it*8 + h*2;
                float2 f = __half22float2(*reinterpret_cast<const __half2*>(&ws[h]));
                if (f.x >= thr) {
                    if (pos < CAND_CAP) g_cand[pos] = ((unsigned)(r0+row)<<10) | c;
                    ++pos;
                }
                if (f.y >= thr) {
                    if (pos < CAND_CAP) g_cand[pos] = ((unsigned)(r0+row)<<10) | (c+1);
                    ++pos;
                }
            }
        }
    }
}

__global__ void k_pick2(const float* __restrict__ cb){
    int total = g_ncand; if (total > CAND_CAP) total = CAND_CAP;
    for (int i = blockIdx.x*blockDim.x + threadIdx.x; i < total; i += gridDim.x*blockDim.x) {
        unsigned e = g_cand[i];
        int n = (int)(e>>10), code = (int)(e & 1023u);
        const float4* zp = (const float4*)(g_z + (size_t)n*CD);
        const float4* cp = (const float4*)(cb + (size_t)code*CD);
        float m = 0.f;
        #pragma unroll 8
        for (int q = 0; q < 64; ++q) {
            float4 a = zp[q], b = cp[q];
            m = __fmaf_rn(a.x,b.x,m); m = __fmaf_rn(a.y,b.y,m);
            m = __fmaf_rn(a.z,b.z,m); m = __fmaf_rn(a.w,b.w,m);
        }
        float t = __fadd_rn(g_znorm[n], -__fadd_rn(m,m));
        float d = __fadd_rn(t, g_cnorm[code]);
        unsigned long long key = ((unsigned long long)__float_as_uint(d)<<32) | (unsigned)code;
        atomicMin(&g_key[n], key);
    }
}

__global__ void k_pick3(float* __restrict__ idx_out){
    __shared__ float sm[256];
    int t = threadIdx.x, n = blockIdx.x*256 + t;
    unsigned long long k = g_key[n];
    int bi = (int)(k & 0xffffffffu);
    g_idx[n] = bi;
    float* op = idx_out ? idx_out : g_idxf_dummy;
    op[n] = (float)bi;
    sm[t] = __uint_as_float((unsigned)(k>>32));
    __syncthreads();
    for (int s = 128; s; s >>= 1) { if (t < s) sm[t] += sm[t+s]; __syncthreads(); }
    if (!t) g_part[blockIdx.x] = sm[0];
}

__global__ void k_decode(const float* __restrict__ dec_b, float* __restrict__ out){
    int t = blockIdx.x*256 + threadIdx.x;
    int v = t<<2;
    int j = (v>>2)&63, y = (v>>8)&255, bo = v>>16;
    int b = bo/3, o = bo - b*3, i = y>>2, ki = y&3;
    int n = (b<<12) + (i<<6) + j;
    int id = g_idx[n];
    float4 w = *(const float4*)&g_cb3[id*PATCH + o*16 + (ki<<2)];
    float bb = dec_b[o];
    ((float4*)out)[t] = make_float4(w.x+bb, w.y+bb, w.z+bb, w.w+bb);
}

__global__ void k_loss2(float* __restrict__ lo){
    __shared__ float sm[256]; int t = threadIdx.x;
    sm[t] = g_part[t]; __syncthreads();
    for (int s = 128; s; s >>= 1) { if (t < s) sm[t] += sm[t+s]; __syncthreads(); }
    if (!t) *lo = 1.25f * sm[0] / 16777216.0f;
}

extern "C" void kernel_launch(void* const* d_in, const int* in_sizes, int n_in,
                              void* d_out, int out_size){
    const float* x     = (const float*)d_in[0];
    const float* enc_w = (const float*)d_in[1];
    const float* enc_b = (const float*)d_in[2];
    const float* w1    = (const float*)d_in[3];
    const float* b1    = (const float*)d_in[4];
    const float* cb    = (const float*)d_in[5];
    const float* w2    = (const float*)d_in[6];
    const float* b2    = (const float*)d_in[7];
    const float* dw    = (const float*)d_in[8];
    const float* db    = (const float*)d_in[9];
    float* out = (float*)d_out;

    static bool attr_done = false;
    if (!attr_done) {
        cudaFuncSetAttribute(k_score, cudaFuncAttributeMaxDynamicSharedMemorySize, SC_SMEM);
        cudaFuncSetAttribute(k_z, cudaFuncAttributeMaxDynamicSharedMemorySize, KZ_SMEM);
        attr_done = true;
    }

    k_prep <<<437, 256>>>(enc_w, enc_b, w1, b1, cb);
    k_G    <<<49, 256>>>(w2, dw, b2);
    k_cb3  <<<1024, 192>>>(cb);
    k_z    <<<dim3(512,2), 256, KZ_SMEM>>>(x);
    k_score<<<1024, 256, SC_SMEM>>>();
    k_pick2<<<2048, 128>>>(cb);

    bool has_idx  = out_size >= 3145728 + 65536;
    bool has_loss = out_size >= 3145728 + 65536 + 1;
    k_pick3<<<256, 256>>>(has_idx ? out + 3145728 : nullptr);
    k_decode<<<3072, 256>>>(db, out);
    if (has_loss) k_loss2<<<1, 256>>>(out + 3145728 + 65536);
}